// round 1
// baseline (speedup 1.0000x reference)
#include <cuda_runtime.h>
#include <math.h>

#define B 8
#define D 256
#define C 1024
#define HW 1024

// ---------------- scratch (device globals; zeroed-by-kernel where atomically accumulated) ----
__device__ float g_A [B*C*HW];    // gelu(expand GEMM) pre-BN1   (32 MB)
__device__ float g_B2[B*C*HW];    // gelu(dyn conv)   pre-BN2   (32 MB)
__device__ float g_Z [B*D*HW];    // projection out   pre-BN3   (8 MB)
__device__ float g_Sbo[B*C], g_SSbo[B*C];                 // atomics (zeroed each launch)
__device__ float g_scale1[C], g_shift1[C];
__device__ float g_gap[B*C];
__device__ float g_kw[B*9];
__device__ float g_S2[B*C], g_SS2[B*C], g_Mx2[B*C], g_Mn2[B*C];
__device__ float g_scale2[C], g_shift2[C];
__device__ float g_avg2[B*C], g_max2[B*C];
__device__ float g_Acoef[B*C], g_Bcoef[B*C];
__device__ float g_Cbd[B*D];
__device__ float g_spmean[B*HW], g_spmax[B*HW], g_spatt[B*HW];
__device__ float g_Sd3[D], g_SSd3[D];                     // atomics (zeroed each launch)
__device__ float g_scale3[D], g_shift3[D];

__device__ __forceinline__ float gelu_f(float x){
    return 0.5f*x*(1.0f + erff(x*0.70710678118654752440f));
}

// ---------------- zero the atomic accumulators (graph-replay safe) ----------
__global__ void k_zero(){
    int i = blockIdx.x*blockDim.x + threadIdx.x;   // 16*512 = 8192
    if (i < B*C){ g_Sbo[i]=0.f; g_SSbo[i]=0.f; }
    if (i < D)  { g_Sd3[i]=0.f; g_SSd3[i]=0.f; }
}

// ---------------- expand GEMM: Y[b,o,s] = sum_c w1[o,c]*x[b,s,c] + b1 ; gelu; stats -----
__global__ __launch_bounds__(256) void k_gemm1(const float* __restrict__ x,
                                               const float* __restrict__ w1,
                                               const float* __restrict__ b1){
    const int b = blockIdx.z;
    const int oBase = blockIdx.y<<6, sBase = blockIdx.x<<6;
    const int tx = threadIdx.x, ty = threadIdx.y;
    const int tid = ty*16 + tx;
    __shared__ __align__(16) float Ws[16][68];
    __shared__ __align__(16) float Xs[16][68];
    float acc[4][4];
    #pragma unroll
    for (int i=0;i<4;i++){
        #pragma unroll
        for (int j=0;j<4;j++) acc[i][j]=0.f;
    }
    const float* xb = x + (size_t)b*HW*D;
    for (int k0=0;k0<D;k0+=16){
        #pragma unroll
        for (int r=0;r<4;r++){
            int i = tid + (r<<8);
            int o = i>>4, k = i&15;
            Ws[k][o] = w1[(oBase+o)*D + k0 + k];
            Xs[k][o] = xb[(size_t)(sBase+o)*D + k0 + k];
        }
        __syncthreads();
        #pragma unroll
        for (int k=0;k<16;k++){
            float4 wv = *reinterpret_cast<const float4*>(&Ws[k][ty<<2]);
            float4 xv = *reinterpret_cast<const float4*>(&Xs[k][tx<<2]);
            float wr[4] = {wv.x,wv.y,wv.z,wv.w};
            float xr[4] = {xv.x,xv.y,xv.z,xv.w};
            #pragma unroll
            for (int i=0;i<4;i++){
                #pragma unroll
                for (int j=0;j<4;j++) acc[i][j] += wr[i]*xr[j];
            }
        }
        __syncthreads();
    }
    #pragma unroll
    for (int i=0;i<4;i++){
        int o = oBase + (ty<<2) + i;
        float bias = b1[o];
        float s_=0.f, ss_=0.f;
        #pragma unroll
        for (int j=0;j<4;j++){
            float v = gelu_f(acc[i][j] + bias);
            g_A[(((size_t)b*C + o)<<10) + sBase + (tx<<2) + j] = v;
            s_ += v; ss_ += v*v;
        }
        #pragma unroll
        for (int off=8; off; off>>=1){
            s_  += __shfl_down_sync(0xffffffffu, s_,  off, 16);
            ss_ += __shfl_down_sync(0xffffffffu, ss_, off, 16);
        }
        if (tx==0){
            atomicAdd(&g_Sbo [b*C+o], s_);
            atomicAdd(&g_SSbo[b*C+o], ss_);
        }
    }
}

// ---------------- BN1 finalize + GAP of normalized ----------
__global__ void k_bn1fin(const float* __restrict__ g1, const float* __restrict__ be1){
    int o = blockIdx.x*256 + threadIdx.x;
    if (o >= C) return;
    float S=0.f, SS=0.f;
    for (int b=0;b<B;b++){ S += g_Sbo[b*C+o]; SS += g_SSbo[b*C+o]; }
    float m = S*(1.f/8192.f), v = SS*(1.f/8192.f) - m*m;
    float rs = rsqrtf(v + 1e-5f);
    float sc = rs*g1[o], sh = be1[o] - m*sc;
    g_scale1[o]=sc; g_shift1[o]=sh;
    for (int b=0;b<B;b++)
        g_gap[b*C+o] = g_Sbo[b*C+o]*(1.f/1024.f)*sc + sh;
}

// ---------------- dynamic kernel weights: relu FC -> softmax(9) per sample ----------
__global__ void k_dynw(const float* __restrict__ aw1, const float* __restrict__ ab1,
                       const float* __restrict__ aw2, const float* __restrict__ ab2){
    int b = blockIdx.x, t = threadIdx.x; // 128 threads
    __shared__ float h1[128];
    __shared__ float logits[9];
    const float* gapb = &g_gap[b*C];
    float a = ab1[t];
    for (int c=0;c<C;c++) a += aw1[t*C + c]*gapb[c];
    h1[t] = fmaxf(a, 0.f);
    __syncthreads();
    if (t < 9){
        float l = ab2[t];
        for (int j=0;j<128;j++) l += aw2[t*128 + j]*h1[j];
        logits[t] = l;
    }
    __syncthreads();
    if (t == 0){
        float mx = logits[0];
        for (int j=1;j<9;j++) mx = fmaxf(mx, logits[j]);
        float e[9], Zs=0.f;
        for (int j=0;j<9;j++){ e[j]=expf(logits[j]-mx); Zs+=e[j]; }
        float inv = 1.f/Zs;
        for (int j=0;j<9;j++) g_kw[b*9+j] = e[j]*inv;
    }
}

// ---------------- dynamic depthwise conv (on BN1-normalized, zero-pad) + gelu + BN2 stats ---
__global__ __launch_bounds__(256) void k_dynconv(){
    const int o = blockIdx.x, b = blockIdx.y;
    const int tid = threadIdx.x;
    __shared__ float sm[34][35];
    __shared__ float kwsh[9];
    __shared__ float red[256];
    if (tid < 9) kwsh[tid] = g_kw[b*9 + tid];
    const float sc = g_scale1[o], sh = g_shift1[o];
    const float* plane = &g_A[((size_t)(b*C + o))<<10];
    for (int i=tid; i<34*34; i+=256){
        int r = i/34, c = i - r*34;
        int h = r-1, w = c-1;
        float v = 0.f;
        if ((unsigned)h < 32u && (unsigned)w < 32u) v = plane[(h<<5)+w]*sc + sh;
        sm[r][c] = v;
    }
    __syncthreads();
    float lsum=0.f, lss=0.f, lmx=-3.4e38f, lmn=3.4e38f;
    #pragma unroll
    for (int q=0;q<4;q++){
        int p = tid + (q<<8);
        int ph = p>>5, pw_ = p&31;
        float a = 0.f;
        #pragma unroll
        for (int i=0;i<3;i++){
            #pragma unroll
            for (int j=0;j<3;j++) a += kwsh[i*3+j]*sm[ph+i][pw_+j];
        }
        float g = gelu_f(a);
        g_B2[(((size_t)(b*C + o))<<10) + p] = g;
        lsum += g; lss += g*g;
        lmx = fmaxf(lmx, g); lmn = fminf(lmn, g);
    }
    red[tid]=lsum; __syncthreads();
    for (int s=128;s;s>>=1){ if (tid<s) red[tid]+=red[tid+s]; __syncthreads(); }
    if (tid==0) g_S2[b*C+o]=red[0];
    __syncthreads();
    red[tid]=lss; __syncthreads();
    for (int s=128;s;s>>=1){ if (tid<s) red[tid]+=red[tid+s]; __syncthreads(); }
    if (tid==0) g_SS2[b*C+o]=red[0];
    __syncthreads();
    red[tid]=lmx; __syncthreads();
    for (int s=128;s;s>>=1){ if (tid<s) red[tid]=fmaxf(red[tid],red[tid+s]); __syncthreads(); }
    if (tid==0) g_Mx2[b*C+o]=red[0];
    __syncthreads();
    red[tid]=lmn; __syncthreads();
    for (int s=128;s;s>>=1){ if (tid<s) red[tid]=fminf(red[tid],red[tid+s]); __syncthreads(); }
    if (tid==0) g_Mn2[b*C+o]=red[0];
}

// ---------------- BN2 finalize + per-(b,c) normalized avg / max ----------
__global__ void k_bn2fin(const float* __restrict__ g2, const float* __restrict__ be2){
    int o = blockIdx.x*256 + threadIdx.x;
    if (o >= C) return;
    float S=0.f, SS=0.f;
    for (int b=0;b<B;b++){ S += g_S2[b*C+o]; SS += g_SS2[b*C+o]; }
    float m = S*(1.f/8192.f), v = SS*(1.f/8192.f) - m*m;
    float rs = rsqrtf(v + 1e-5f);
    float sc = rs*g2[o], sh = be2[o] - m*sc;
    g_scale2[o]=sc; g_shift2[o]=sh;
    for (int b=0;b<B;b++){
        g_avg2[b*C+o] = g_S2[b*C+o]*(1.f/1024.f)*sc + sh;
        float pre = (sc >= 0.f) ? g_Mx2[b*C+o] : g_Mn2[b*C+o];
        g_max2[b*C+o] = pre*sc + sh;
    }
}

// ---------------- channel attention sigmoid -> fold into (Acoef, Bcoef) ----------
__global__ void k_catt(const float* __restrict__ ca_w1, const float* __restrict__ ca_w2){
    int b = blockIdx.x, tid = threadIdx.x; // 256 threads
    __shared__ float hsum[64];
    if (tid < 64){
        float aa=0.f, am=0.f;
        const float* w  = &ca_w1[tid*C];
        const float* av = &g_avg2[b*C];
        const float* mv = &g_max2[b*C];
        for (int c=0;c<C;c++){ aa += w[c]*av[c]; am += w[c]*mv[c]; }
        hsum[tid] = fmaxf(aa,0.f) + fmaxf(am,0.f);
    }
    __syncthreads();
    for (int c=tid;c<C;c+=256){
        float a = 0.f;
        const float* w2r = &ca_w2[c*64];
        #pragma unroll 8
        for (int j=0;j<64;j++) a += w2r[j]*hsum[j];
        float s = 1.f/(1.f + expf(-a));
        g_Acoef[b*C+c] = s*g_scale2[c];
        g_Bcoef[b*C+c] = s*g_shift2[c];
    }
}

// ---------------- Cbd[b,d] = sum_c pw[d,c]*Bcoef[b,c] ----------
__global__ void k_cbd(const float* __restrict__ pw){
    int b = blockIdx.x, d = threadIdx.x; // 256 threads
    const float* Bc = &g_Bcoef[b*C];
    float a = 0.f;
    for (int c=0;c<C;c++) a += pw[d*C + c]*Bc[c];
    g_Cbd[b*D + d] = a;
}

// ---------------- spatial mean/max over channels of channel-attended tensor ----------
__global__ void k_spstats(){
    int b = blockIdx.y;
    int s = blockIdx.x*128 + threadIdx.x;
    const float* base = &g_B2[((size_t)b)<<20];
    const float* Ac = &g_Acoef[b*C];
    const float* Bc = &g_Bcoef[b*C];
    float sum=0.f, mx=-3.4e38f;
    for (int c=0;c<C;c++){
        float v = Ac[c]*base[(c<<10)+s] + Bc[c];
        sum += v; mx = fmaxf(mx, v);
    }
    g_spmean[b*HW+s] = sum*(1.f/1024.f);
    g_spmax [b*HW+s] = mx;
}

// ---------------- 7x7 spatial conv (pad 3) on [mean;max], sigmoid ----------
__global__ void k_spconv(const float* __restrict__ sw, const float* __restrict__ sb){
    int b = blockIdx.x, tid = threadIdx.x; // 256 threads
    __shared__ float sa[1024], sx[1024];
    __shared__ float kw[98];
    for (int i=tid;i<1024;i+=256){ sa[i]=g_spmean[b*HW+i]; sx[i]=g_spmax[b*HW+i]; }
    if (tid < 98) kw[tid] = sw[tid];
    __syncthreads();
    float bias = sb[0];
    for (int p=tid;p<1024;p+=256){
        int ph = p>>5, pw_ = p&31;
        float acc = bias;
        #pragma unroll
        for (int i=0;i<7;i++){
            int hh = ph + i - 3;
            if ((unsigned)hh >= 32u) continue;
            #pragma unroll
            for (int j=0;j<7;j++){
                int ww = pw_ + j - 3;
                if ((unsigned)ww >= 32u) continue;
                float va = sa[(hh<<5)+ww], vx = sx[(hh<<5)+ww];
                acc += kw[i*7+j]*va + kw[49+i*7+j]*vx;
            }
        }
        g_spatt[b*HW+p] = 1.f/(1.f + expf(-acc));
    }
}

// ---------------- projection GEMM with folded channel att + spatial att; BN3 stats ---------
__global__ __launch_bounds__(256) void k_gemm2(const float* __restrict__ pw,
                                               const float* __restrict__ pb){
    const int b = blockIdx.z;
    const int dBase = blockIdx.y<<6, sBase = blockIdx.x<<6;
    const int tx = threadIdx.x, ty = threadIdx.y;
    const int tid = ty*16 + tx;
    __shared__ __align__(16) float Ws[16][68];
    __shared__ __align__(16) float Xs[16][68];
    float acc[4][4];
    #pragma unroll
    for (int i=0;i<4;i++){
        #pragma unroll
        for (int j=0;j<4;j++) acc[i][j]=0.f;
    }
    const float* Ac  = &g_Acoef[b*C];
    const float* src = &g_B2[((size_t)b)<<20];
    for (int k0=0;k0<C;k0+=16){
        #pragma unroll
        for (int r=0;r<4;r++){
            int i = tid + (r<<8);
            { int o = i>>4, k = i&15; Ws[k][o] = pw[(dBase+o)*C + k0 + k]; }
            { int k = i>>6, s = i&63; Xs[k][s] = src[((k0+k)<<10) + sBase + s]*Ac[k0+k]; }
        }
        __syncthreads();
        #pragma unroll
        for (int k=0;k<16;k++){
            float4 wv = *reinterpret_cast<const float4*>(&Ws[k][ty<<2]);
            float4 xv = *reinterpret_cast<const float4*>(&Xs[k][tx<<2]);
            float wr[4] = {wv.x,wv.y,wv.z,wv.w};
            float xr[4] = {xv.x,xv.y,xv.z,xv.w};
            #pragma unroll
            for (int i=0;i<4;i++){
                #pragma unroll
                for (int j=0;j<4;j++) acc[i][j] += wr[i]*xr[j];
            }
        }
        __syncthreads();
    }
    float spv[4];
    #pragma unroll
    for (int j=0;j<4;j++) spv[j] = g_spatt[b*HW + sBase + (tx<<2) + j];
    #pragma unroll
    for (int i=0;i<4;i++){
        int d = dBase + (ty<<2) + i;
        float cb = g_Cbd[b*D + d], bias = pb[d];
        float s_=0.f, ss_=0.f;
        #pragma unroll
        for (int j=0;j<4;j++){
            float z = spv[j]*(acc[i][j] + cb) + bias;
            g_Z[(((size_t)b*D + d)<<10) + sBase + (tx<<2) + j] = z;
            s_ += z; ss_ += z*z;
        }
        #pragma unroll
        for (int off=8; off; off>>=1){
            s_  += __shfl_down_sync(0xffffffffu, s_,  off, 16);
            ss_ += __shfl_down_sync(0xffffffffu, ss_, off, 16);
        }
        if (tx==0){
            atomicAdd(&g_Sd3 [d], s_);
            atomicAdd(&g_SSd3[d], ss_);
        }
    }
}

// ---------------- BN3 finalize ----------
__global__ void k_bn3fin(const float* __restrict__ g3, const float* __restrict__ be3){
    int d = threadIdx.x;
    float m = g_Sd3[d]*(1.f/8192.f);
    float v = g_SSd3[d]*(1.f/8192.f) - m*m;
    float sc = rsqrtf(v + 1e-5f)*g3[d];
    g_scale3[d] = sc;
    g_shift3[d] = be3[d] - m*sc;
}

// ---------------- transpose (b,d,s)->(b,s,d), BN3 affine, residual add ----------
__global__ void k_out(const float* __restrict__ x, float* __restrict__ out){
    const int b = blockIdx.z;
    const int dB = blockIdx.y<<5, sB = blockIdx.x<<5;
    const int tx = threadIdx.x, ty = threadIdx.y; // (32,8)
    __shared__ float sm[32][33];
    #pragma unroll
    for (int r=0;r<4;r++){
        int dd = ty + (r<<3);
        sm[dd][tx] = g_Z[(((size_t)b*D + dB + dd)<<10) + sB + tx];
    }
    __syncthreads();
    int d = dB + tx;
    float sc = g_scale3[d], sh = g_shift3[d];
    #pragma unroll
    for (int r=0;r<4;r++){
        int ss = ty + (r<<3);
        size_t oi = ((size_t)(b*HW) + sB + ss)*D + d;
        out[oi] = x[oi] + sm[tx][ss]*sc + sh;
    }
}

extern "C" void kernel_launch(void* const* d_in, const int* in_sizes, int n_in,
                              void* d_out, int out_size){
    const float* x     = (const float*)d_in[0];
    const float* w1    = (const float*)d_in[1];
    const float* b1    = (const float*)d_in[2];
    const float* g1    = (const float*)d_in[3];
    const float* be1   = (const float*)d_in[4];
    const float* aw1   = (const float*)d_in[5];
    const float* ab1   = (const float*)d_in[6];
    const float* aw2   = (const float*)d_in[7];
    const float* ab2   = (const float*)d_in[8];
    const float* g2    = (const float*)d_in[9];
    const float* be2   = (const float*)d_in[10];
    const float* ca_w1 = (const float*)d_in[11];
    const float* ca_w2 = (const float*)d_in[12];
    const float* pw    = (const float*)d_in[13];
    const float* pb    = (const float*)d_in[14];
    const float* g3    = (const float*)d_in[15];
    const float* be3   = (const float*)d_in[16];
    const float* sw    = (const float*)d_in[17];
    const float* sb    = (const float*)d_in[18];
    float* out = (float*)d_out;

    k_zero   <<<16, 512>>>();
    k_gemm1  <<<dim3(16,16,B), dim3(16,16)>>>(x, w1, b1);
    k_bn1fin <<<4, 256>>>(g1, be1);
    k_dynw   <<<B, 128>>>(aw1, ab1, aw2, ab2);
    k_dynconv<<<dim3(C,B), 256>>>();
    k_bn2fin <<<4, 256>>>(g2, be2);
    k_catt   <<<B, 256>>>(ca_w1, ca_w2);
    k_cbd    <<<B, 256>>>(pw);
    k_spstats<<<dim3(8,B), 128>>>();
    k_spconv <<<B, 256>>>(sw, sb);
    k_gemm2  <<<dim3(16,4,B), dim3(16,16)>>>(pw, pb);
    k_bn3fin <<<1, 256>>>(g3, be3);
    k_out    <<<dim3(32,8,B), dim3(32,8)>>>(x, out);
}

// round 3
// speedup vs baseline: 1.9414x; 1.9414x over previous
#include <cuda_runtime.h>
#include <math.h>

#define B 8
#define D 256
#define C 1024
#define HW 1024

typedef unsigned long long u64;

// ---------------- scratch ----------------
__device__ float g_A [B*C*HW];
__device__ float g_B2[B*C*HW];
__device__ float g_Z [B*D*HW];
__device__ float g_Sbo[B*C], g_SSbo[B*C];
__device__ float g_scale1[C], g_shift1[C];
__device__ float g_gap[B*C];
__device__ float g_kw[B*9];
__device__ float g_S2[B*C], g_SS2[B*C], g_Mx2[B*C], g_Mn2[B*C];
__device__ float g_scale2[C], g_shift2[C];
__device__ float g_avg2[B*C], g_max2[B*C];
__device__ float g_Acoef[B*C], g_Bcoef[B*C];
__device__ float g_Cbd[B*D];
__device__ float g_spmean[B*HW], g_spmax[B*HW], g_spatt[B*HW];
__device__ float g_Sd3[D], g_SSd3[D];
__device__ float g_scale3[D], g_shift3[D];

__device__ __forceinline__ float gelu_f(float x){
    return 0.5f*x*(1.0f + erff(x*0.70710678118654752440f));
}
__device__ __forceinline__ u64 splat2(float v){
    unsigned u = __float_as_uint(v);
    u64 r; asm("mov.b64 %0, {%1, %2};" : "=l"(r) : "r"(u), "r"(u)); return r;
}
__device__ __forceinline__ float2 unpack2(u64 v){
    unsigned a, bb; asm("mov.b64 {%0, %1}, %2;" : "=r"(a), "=r"(bb) : "l"(v));
    return make_float2(__uint_as_float(a), __uint_as_float(bb));
}
__device__ __forceinline__ void fma2(u64 &d, u64 a, u64 b){
    asm("fma.rn.f32x2 %0, %1, %2, %0;" : "+l"(d) : "l"(a), "l"(b));
}
__device__ __forceinline__ u64 fma2o(u64 a, u64 b, u64 c){
    u64 d; asm("fma.rn.f32x2 %0, %1, %2, %3;" : "=l"(d) : "l"(a), "l"(b), "l"(c)); return d;
}
__device__ __forceinline__ u64 add2(u64 a, u64 b){
    u64 d; asm("add.rn.f32x2 %0, %1, %2;" : "=l"(d) : "l"(a), "l"(b)); return d;
}

// ---------------- zero accumulators ----------------
__global__ void k_zero(){
    int i = blockIdx.x*blockDim.x + threadIdx.x;
    if (i < B*C){ g_Sbo[i]=0.f; g_SSbo[i]=0.f; }
    if (i < D)  { g_Sd3[i]=0.f; g_SSd3[i]=0.f; }
}

// ================= GEMM1: 128x128 tile, f32x2, gelu + BN1 stats =================
__global__ __launch_bounds__(256) void k_gemm1(const float* __restrict__ x,
                                               const float* __restrict__ w1,
                                               const float* __restrict__ b1){
    const int b = blockIdx.z;
    const int oBase = blockIdx.y<<7, sBase = blockIdx.x<<7;
    const int tx = threadIdx.x, ty = threadIdx.y;   // 16x16
    const int tid = ty*16 + tx;
    __shared__ u64   Wsp[8][130];
    __shared__ float Xs [8][132];

    u64 acc[8][4];
    #pragma unroll
    for (int i=0;i<8;i++){
        #pragma unroll
        for (int j=0;j<4;j++) acc[i][j]=0ull;
    }

    const float* xb = x + (size_t)b*HW*D;
    const int rowL = tid>>1, kpL = (tid&1)*4;
    const float* wp = w1 + (size_t)(oBase+rowL)*D + kpL;
    const float* xp_ = xb + (size_t)(sBase+rowL)*D + kpL;

    float4 wv = *reinterpret_cast<const float4*>(wp);
    float4 xv = *reinterpret_cast<const float4*>(xp_);

    for (int k0=0;k0<D;k0+=8){
        Wsp[kpL+0][rowL] = splat2(wv.x);
        Wsp[kpL+1][rowL] = splat2(wv.y);
        Wsp[kpL+2][rowL] = splat2(wv.z);
        Wsp[kpL+3][rowL] = splat2(wv.w);
        Xs[kpL+0][rowL] = xv.x; Xs[kpL+1][rowL] = xv.y;
        Xs[kpL+2][rowL] = xv.z; Xs[kpL+3][rowL] = xv.w;
        __syncthreads();
        if (k0+8 < D){
            wv = *reinterpret_cast<const float4*>(wp + k0 + 8);
            xv = *reinterpret_cast<const float4*>(xp_ + k0 + 8);
        }
        #pragma unroll
        for (int k=0;k<8;k++){
            u64 w2[8], x2[4];
            #pragma unroll
            for (int i=0;i<8;i++) w2[i] = Wsp[k][(ty<<2)+(i&3)+((i>>2)<<6)];
            #pragma unroll
            for (int j=0;j<4;j++) x2[j] = *reinterpret_cast<const u64*>(&Xs[k][(tx<<2)+((j>>1)<<6)+((j&1)<<1)]);
            #pragma unroll
            for (int i=0;i<8;i++){
                #pragma unroll
                for (int j=0;j<4;j++) fma2(acc[i][j], w2[i], x2[j]);
            }
        }
        __syncthreads();
    }
    #pragma unroll
    for (int i=0;i<8;i++){
        int o = oBase + (ty<<2) + (i&3) + ((i>>2)<<6);
        float bias = b1[o];
        float s_=0.f, ss_=0.f;
        float* dst = &g_A[(((size_t)b*C + o)<<10)];
        #pragma unroll
        for (int j=0;j<4;j++){
            int s0 = sBase + (tx<<2) + ((j>>1)<<6) + ((j&1)<<1);
            float2 v = unpack2(acc[i][j]);
            float v0 = gelu_f(v.x + bias), v1 = gelu_f(v.y + bias);
            *reinterpret_cast<float2*>(&dst[s0]) = make_float2(v0, v1);
            s_ += v0 + v1; ss_ += v0*v0 + v1*v1;
        }
        #pragma unroll
        for (int off=8; off; off>>=1){
            s_  += __shfl_down_sync(0xffffffffu, s_,  off, 16);
            ss_ += __shfl_down_sync(0xffffffffu, ss_, off, 16);
        }
        if (tx==0){
            atomicAdd(&g_Sbo [b*C+o], s_);
            atomicAdd(&g_SSbo[b*C+o], ss_);
        }
    }
}

// ---------------- BN1 finalize + GAP ----------------
__global__ void k_bn1fin(const float* __restrict__ g1, const float* __restrict__ be1){
    int o = blockIdx.x*256 + threadIdx.x;
    if (o >= C) return;
    float S=0.f, SS=0.f;
    for (int b=0;b<B;b++){ S += g_Sbo[b*C+o]; SS += g_SSbo[b*C+o]; }
    float m = S*(1.f/8192.f), v = SS*(1.f/8192.f) - m*m;
    float rs = rsqrtf(v + 1e-5f);
    float sc = rs*g1[o], sh = be1[o] - m*sc;
    g_scale1[o]=sc; g_shift1[o]=sh;
    for (int b=0;b<B;b++)
        g_gap[b*C+o] = g_Sbo[b*C+o]*(1.f/1024.f)*sc + sh;
}

// ---------------- dynamic kernel weights (warp-per-output) ----------------
__global__ __launch_bounds__(1024) void k_dynw(const float* __restrict__ aw1, const float* __restrict__ ab1,
                                               const float* __restrict__ aw2, const float* __restrict__ ab2){
    int b = blockIdx.x, tid = threadIdx.x;
    int w = tid>>5, lane = tid&31;
    __shared__ float gap[C];
    __shared__ float h1[128];
    __shared__ float logits[9];
    for (int i=tid;i<C;i+=1024) gap[i] = g_gap[b*C+i];
    __syncthreads();
    #pragma unroll
    for (int r=0;r<4;r++){
        int o = (w<<2) + r;
        const float* row = &aw1[(size_t)o*C];
        float a = 0.f;
        #pragma unroll 8
        for (int c=lane;c<C;c+=32) a += row[c]*gap[c];
        #pragma unroll
        for (int off=16;off;off>>=1) a += __shfl_down_sync(0xffffffffu, a, off);
        if (lane==0) h1[o] = fmaxf(a + ab1[o], 0.f);
    }
    __syncthreads();
    if (w==0 && lane<9){
        float l = ab2[lane];
        const float* row = &aw2[lane*128];
        #pragma unroll 16
        for (int j=0;j<128;j++) l += row[j]*h1[j];
        logits[lane] = l;
    }
    __syncthreads();
    if (tid==0){
        float mx = logits[0];
        for (int j=1;j<9;j++) mx = fmaxf(mx, logits[j]);
        float e[9], Zs=0.f;
        for (int j=0;j<9;j++){ e[j]=expf(logits[j]-mx); Zs+=e[j]; }
        float inv = 1.f/Zs;
        for (int j=0;j<9;j++) g_kw[b*9+j] = e[j]*inv;
    }
}

// ---------------- dynamic depthwise conv + gelu + BN2 stats ----------------
__global__ __launch_bounds__(256) void k_dynconv(){
    const int o = blockIdx.x, b = blockIdx.y;
    const int tid = threadIdx.x;
    const int w = tid>>5, lane = tid&31;
    __shared__ float sm[34][35];
    __shared__ float kwsh[9];
    __shared__ float r4[4][8];
    if (tid < 9) kwsh[tid] = g_kw[b*9 + tid];
    const float sc = g_scale1[o], sh = g_shift1[o];
    const float* plane = &g_A[((size_t)(b*C + o))<<10];
    for (int i=tid; i<34*34; i+=256){
        int r = i/34, c = i - r*34;
        int h = r-1, ww = c-1;
        float v = 0.f;
        if ((unsigned)h < 32u && (unsigned)ww < 32u) v = plane[(h<<5)+ww]*sc + sh;
        sm[r][c] = v;
    }
    __syncthreads();
    float lsum=0.f, lss=0.f, lmx=-3.4e38f, lmn=3.4e38f;
    #pragma unroll
    for (int q=0;q<4;q++){
        int p = tid + (q<<8);
        int ph = p>>5, pw_ = p&31;
        float a = 0.f;
        #pragma unroll
        for (int i=0;i<3;i++){
            #pragma unroll
            for (int j=0;j<3;j++) a += kwsh[i*3+j]*sm[ph+i][pw_+j];
        }
        float g = gelu_f(a);
        g_B2[(((size_t)(b*C + o))<<10) + p] = g;
        lsum += g; lss += g*g;
        lmx = fmaxf(lmx, g); lmn = fminf(lmn, g);
    }
    #pragma unroll
    for (int off=16;off;off>>=1){
        lsum += __shfl_down_sync(0xffffffffu, lsum, off);
        lss  += __shfl_down_sync(0xffffffffu, lss,  off);
        lmx = fmaxf(lmx, __shfl_down_sync(0xffffffffu, lmx, off));
        lmn = fminf(lmn, __shfl_down_sync(0xffffffffu, lmn, off));
    }
    if (lane==0){ r4[0][w]=lsum; r4[1][w]=lss; r4[2][w]=lmx; r4[3][w]=lmn; }
    __syncthreads();
    if (tid==0){
        float S=0,SS=0,MX=-3.4e38f,MN=3.4e38f;
        for (int i=0;i<8;i++){ S+=r4[0][i]; SS+=r4[1][i]; MX=fmaxf(MX,r4[2][i]); MN=fminf(MN,r4[3][i]); }
        g_S2[b*C+o]=S; g_SS2[b*C+o]=SS; g_Mx2[b*C+o]=MX; g_Mn2[b*C+o]=MN;
    }
}

// ---------------- BN2 finalize ----------------
__global__ void k_bn2fin(const float* __restrict__ g2, const float* __restrict__ be2){
    int o = blockIdx.x*256 + threadIdx.x;
    if (o >= C) return;
    float S=0.f, SS=0.f;
    for (int b=0;b<B;b++){ S += g_S2[b*C+o]; SS += g_SS2[b*C+o]; }
    float m = S*(1.f/8192.f), v = SS*(1.f/8192.f) - m*m;
    float rs = rsqrtf(v + 1e-5f);
    float sc = rs*g2[o], sh = be2[o] - m*sc;
    g_scale2[o]=sc; g_shift2[o]=sh;
    for (int b=0;b<B;b++){
        g_avg2[b*C+o] = g_S2[b*C+o]*(1.f/1024.f)*sc + sh;
        float pre = (sc >= 0.f) ? g_Mx2[b*C+o] : g_Mn2[b*C+o];
        g_max2[b*C+o] = pre*sc + sh;
    }
}

// ---------------- channel attention + Cbd fused (block per b, 512 thr) ----------------
__global__ __launch_bounds__(512) void k_cattcbd(const float* __restrict__ ca_w1,
                                                 const float* __restrict__ ca_w2,
                                                 const float* __restrict__ pw){
    int b = blockIdx.x, tid = threadIdx.x;
    int w = tid>>5, lane = tid&31;
    __shared__ float sav[C], smv[C], hsum[64], sBc[C];
    for (int i=tid;i<C;i+=512){ sav[i]=g_avg2[b*C+i]; smv[i]=g_max2[b*C+i]; }
    __syncthreads();
    #pragma unroll
    for (int r=0;r<4;r++){
        int o = (w<<2) + r;
        const float* row = &ca_w1[(size_t)o*C];
        float aa=0.f, am=0.f;
        #pragma unroll 8
        for (int c=lane;c<C;c+=32){ float rv=row[c]; aa += rv*sav[c]; am += rv*smv[c]; }
        #pragma unroll
        for (int off=16;off;off>>=1){
            aa += __shfl_down_sync(0xffffffffu, aa, off);
            am += __shfl_down_sync(0xffffffffu, am, off);
        }
        if (lane==0) hsum[o] = fmaxf(aa,0.f) + fmaxf(am,0.f);
    }
    __syncthreads();
    #pragma unroll
    for (int r=0;r<2;r++){
        int c = tid + (r<<9);
        const float4* w2r = reinterpret_cast<const float4*>(&ca_w2[(size_t)c*64]);
        float a = 0.f;
        #pragma unroll
        for (int j=0;j<16;j++){
            float4 q = w2r[j];
            const float* hh = &hsum[j*4];
            a += q.x*hh[0] + q.y*hh[1] + q.z*hh[2] + q.w*hh[3];
        }
        float s = 1.f/(1.f + expf(-a));
        float Av = s*g_scale2[c], Bv = s*g_shift2[c];
        g_Acoef[b*C+c] = Av; g_Bcoef[b*C+c] = Bv; sBc[c] = Bv;
    }
    __syncthreads();
    #pragma unroll
    for (int r=0;r<16;r++){
        int d = w + (r<<4);
        const float* row = &pw[(size_t)d*C];
        float a = 0.f;
        #pragma unroll 8
        for (int c=lane;c<C;c+=32) a += row[c]*sBc[c];
        #pragma unroll
        for (int off=16;off;off>>=1) a += __shfl_down_sync(0xffffffffu, a, off);
        if (lane==0) g_Cbd[b*D+d] = a;
    }
}

// ---------------- spatial mean/max over channels ----------------
__global__ __launch_bounds__(256) void k_spstats(){
    int b = blockIdx.y;
    int sl = threadIdx.x & 63, cg = threadIdx.x >> 6;
    int s = blockIdx.x*64 + sl;
    __shared__ float rs[4][64], rm[4][64];
    const float* base = &g_B2[((size_t)b)<<20];
    const float* Ac = &g_Acoef[b*C];
    const float* Bc = &g_Bcoef[b*C];
    float sum=0.f, mx=-3.4e38f;
    int c0 = cg*256;
    #pragma unroll 4
    for (int c=c0;c<c0+256;c++){
        float v = Ac[c]*base[(c<<10)+s] + Bc[c];
        sum += v; mx = fmaxf(mx, v);
    }
    rs[cg][sl]=sum; rm[cg][sl]=mx;
    __syncthreads();
    if (threadIdx.x < 64){
        float S = rs[0][sl]+rs[1][sl]+rs[2][sl]+rs[3][sl];
        float M = fmaxf(fmaxf(rm[0][sl],rm[1][sl]),fmaxf(rm[2][sl],rm[3][sl]));
        g_spmean[b*HW+s] = S*(1.f/1024.f);
        g_spmax [b*HW+s] = M;
    }
}

// ---------------- 7x7 spatial conv + sigmoid ----------------
__global__ void k_spconv(const float* __restrict__ sw, const float* __restrict__ sb){
    int b = blockIdx.x, tid = threadIdx.x;
    __shared__ float sa[1024], sx[1024];
    __shared__ float kw[98];
    for (int i=tid;i<1024;i+=256){ sa[i]=g_spmean[b*HW+i]; sx[i]=g_spmax[b*HW+i]; }
    if (tid < 98) kw[tid] = sw[tid];
    __syncthreads();
    float bias = sb[0];
    for (int p=tid;p<1024;p+=256){
        int ph = p>>5, pw_ = p&31;
        float acc = bias;
        #pragma unroll
        for (int i=0;i<7;i++){
            int hh = ph + i - 3;
            if ((unsigned)hh >= 32u) continue;
            #pragma unroll
            for (int j=0;j<7;j++){
                int ww = pw_ + j - 3;
                if ((unsigned)ww >= 32u) continue;
                acc += kw[i*7+j]*sa[(hh<<5)+ww] + kw[49+i*7+j]*sx[(hh<<5)+ww];
            }
        }
        g_spatt[b*HW+p] = 1.f/(1.f + expf(-acc));
    }
}

// ================= GEMM2: 128x128 tile, f32x2, folded attention + BN3 stats =================
__global__ __launch_bounds__(256) void k_gemm2(const float* __restrict__ pw,
                                               const float* __restrict__ pb){
    const int b = blockIdx.z;
    const int dBase = blockIdx.y<<7, sBase = blockIdx.x<<7;
    const int tx = threadIdx.x, ty = threadIdx.y;
    const int tid = ty*16 + tx;
    __shared__ u64   Wsp[8][130];
    __shared__ float Xs [8][132];

    u64 acc[8][4];
    #pragma unroll
    for (int i=0;i<8;i++){
        #pragma unroll
        for (int j=0;j<4;j++) acc[i][j]=0ull;
    }

    const float* Ac  = &g_Acoef[b*C];
    const float* src = &g_B2[((size_t)b)<<20];
    const int rowW = tid>>1, kpW = (tid&1)*4;
    const int kX = tid>>5, spX = (tid&31)*4;
    const float* wp = pw + (size_t)(dBase+rowW)*C + kpW;
    const float* xp_ = src + ((size_t)kX<<10) + sBase + spX;

    float4 wv = *reinterpret_cast<const float4*>(wp);
    float4 xv = *reinterpret_cast<const float4*>(xp_);
    float  av = Ac[kX];

    for (int k0=0;k0<C;k0+=8){
        Wsp[kpW+0][rowW] = splat2(wv.x);
        Wsp[kpW+1][rowW] = splat2(wv.y);
        Wsp[kpW+2][rowW] = splat2(wv.z);
        Wsp[kpW+3][rowW] = splat2(wv.w);
        float4 xs = make_float4(xv.x*av, xv.y*av, xv.z*av, xv.w*av);
        *reinterpret_cast<float4*>(&Xs[kX][spX]) = xs;
        __syncthreads();
        if (k0+8 < C){
            wv = *reinterpret_cast<const float4*>(wp + k0 + 8);
            xv = *reinterpret_cast<const float4*>(xp_ + ((size_t)(k0+8)<<10));
            av = Ac[k0+8+kX];
        }
        #pragma unroll
        for (int k=0;k<8;k++){
            u64 w2[8], x2[4];
            #pragma unroll
            for (int i=0;i<8;i++) w2[i] = Wsp[k][(ty<<2)+(i&3)+((i>>2)<<6)];
            #pragma unroll
            for (int j=0;j<4;j++) x2[j] = *reinterpret_cast<const u64*>(&Xs[k][(tx<<2)+((j>>1)<<6)+((j&1)<<1)]);
            #pragma unroll
            for (int i=0;i<8;i++){
                #pragma unroll
                for (int j=0;j<4;j++) fma2(acc[i][j], w2[i], x2[j]);
            }
        }
        __syncthreads();
    }
    u64 sp2[4];
    #pragma unroll
    for (int j=0;j<4;j++){
        int s0 = sBase + (tx<<2) + ((j>>1)<<6) + ((j&1)<<1);
        sp2[j] = *reinterpret_cast<const u64*>(&g_spatt[b*HW + s0]);
    }
    #pragma unroll
    for (int i=0;i<8;i++){
        int d = dBase + (ty<<2) + (i&3) + ((i>>2)<<6);
        u64 cb2 = splat2(g_Cbd[b*D + d]);
        u64 pb2 = splat2(pb[d]);
        float s_=0.f, ss_=0.f;
        float* dst = &g_Z[(((size_t)b*D + d)<<10)];
        #pragma unroll
        for (int j=0;j<4;j++){
            int s0 = sBase + (tx<<2) + ((j>>1)<<6) + ((j&1)<<1);
            u64 z2 = fma2o(sp2[j], add2(acc[i][j], cb2), pb2);
            *reinterpret_cast<u64*>(&dst[s0]) = z2;
            float2 z = unpack2(z2);
            s_ += z.x + z.y; ss_ += z.x*z.x + z.y*z.y;
        }
        #pragma unroll
        for (int off=8; off; off>>=1){
            s_  += __shfl_down_sync(0xffffffffu, s_,  off, 16);
            ss_ += __shfl_down_sync(0xffffffffu, ss_, off, 16);
        }
        if (tx==0){
            atomicAdd(&g_Sd3 [d], s_);
            atomicAdd(&g_SSd3[d], ss_);
        }
    }
}

// ---------------- BN3 finalize ----------------
__global__ void k_bn3fin(const float* __restrict__ g3, const float* __restrict__ be3){
    int d = threadIdx.x;
    float m = g_Sd3[d]*(1.f/8192.f);
    float v = g_SSd3[d]*(1.f/8192.f) - m*m;
    float sc = rsqrtf(v + 1e-5f)*g3[d];
    g_scale3[d] = sc;
    g_shift3[d] = be3[d] - m*sc;
}

// ---------------- transpose + BN3 + residual ----------------
__global__ void k_out(const float* __restrict__ x, float* __restrict__ out){
    const int b = blockIdx.z;
    const int dB = blockIdx.y<<5, sB = blockIdx.x<<5;
    const int tx = threadIdx.x, ty = threadIdx.y;
    __shared__ float sm[32][33];
    #pragma unroll
    for (int r=0;r<4;r++){
        int dd = ty + (r<<3);
        sm[dd][tx] = g_Z[(((size_t)b*D + dB + dd)<<10) + sB + tx];
    }
    __syncthreads();
    int d = dB + tx;
    float sc = g_scale3[d], sh = g_shift3[d];
    #pragma unroll
    for (int r=0;r<4;r++){
        int ss = ty + (r<<3);
        size_t oi = ((size_t)(b*HW) + sB + ss)*D + d;
        out[oi] = x[oi] + sm[tx][ss]*sc + sh;
    }
}

extern "C" void kernel_launch(void* const* d_in, const int* in_sizes, int n_in,
                              void* d_out, int out_size){
    const float* x     = (const float*)d_in[0];
    const float* w1    = (const float*)d_in[1];
    const float* b1    = (const float*)d_in[2];
    const float* g1    = (const float*)d_in[3];
    const float* be1   = (const float*)d_in[4];
    const float* aw1   = (const float*)d_in[5];
    const float* ab1   = (const float*)d_in[6];
    const float* aw2   = (const float*)d_in[7];
    const float* ab2   = (const float*)d_in[8];
    const float* g2    = (const float*)d_in[9];
    const float* be2   = (const float*)d_in[10];
    const float* ca_w1 = (const float*)d_in[11];
    const float* ca_w2 = (const float*)d_in[12];
    const float* pw    = (const float*)d_in[13];
    const float* pb    = (const float*)d_in[14];
    const float* g3    = (const float*)d_in[15];
    const float* be3   = (const float*)d_in[16];
    const float* sw    = (const float*)d_in[17];
    const float* sb    = (const float*)d_in[18];
    float* out = (float*)d_out;

    k_zero    <<<16, 512>>>();
    k_gemm1   <<<dim3(8,8,B), dim3(16,16)>>>(x, w1, b1);
    k_bn1fin  <<<4, 256>>>(g1, be1);
    k_dynw    <<<B, 1024>>>(aw1, ab1, aw2, ab2);
    k_dynconv <<<dim3(C,B), 256>>>();
    k_bn2fin  <<<4, 256>>>(g2, be2);
    k_cattcbd <<<B, 512>>>(ca_w1, ca_w2, pw);
    k_spstats <<<dim3(16,B), 256>>>();
    k_spconv  <<<B, 256>>>(sw, sb);
    k_gemm2   <<<dim3(8,2,B), dim3(16,16)>>>(pw, pb);
    k_bn3fin  <<<1, 256>>>(g3, be3);
    k_out     <<<dim3(32,8,B), dim3(32,8)>>>(x, out);
}

// round 4
// speedup vs baseline: 2.3618x; 1.2165x over previous
#include <cuda_runtime.h>
#include <math.h>

#define B 8
#define D 256
#define C 1024
#define HW 1024

typedef unsigned long long u64;

// ---------------- scratch ----------------
__device__ float g_A [B*C*HW];
__device__ float g_B2[B*C*HW];
__device__ float g_Z [B*D*HW];
__device__ float g_Sbo[B*C], g_SSbo[B*C];
__device__ float g_scale1[C], g_shift1[C];
__device__ float g_gap[B*C];
__device__ float g_h1[B*128];
__device__ float g_kw[B*9];
__device__ float g_S2[B*C], g_SS2[B*C], g_Mx2[B*C], g_Mn2[B*C];
__device__ float g_scale2[C], g_shift2[C];
__device__ float g_avg2[B*C], g_max2[B*C];
__device__ float g_Acoef[B*C], g_Bcoef[B*C];
__device__ float g_Cbd[B*D];
__device__ float g_sppsum[4*B*HW], g_sppmax[4*B*HW];
__device__ float g_spatt[B*HW];
__device__ float g_Sd3[D], g_SSd3[D];
__device__ float g_scale3[D], g_shift3[D];

__device__ __forceinline__ float gelu_f(float x){
    return 0.5f*x*(1.0f + erff(x*0.70710678118654752440f));
}
__device__ __forceinline__ u64 splat2(float v){
    unsigned u = __float_as_uint(v);
    u64 r; asm("mov.b64 %0, {%1, %2};" : "=l"(r) : "r"(u), "r"(u)); return r;
}
__device__ __forceinline__ float2 unpack2(u64 v){
    unsigned a, bb; asm("mov.b64 {%0, %1}, %2;" : "=r"(a), "=r"(bb) : "l"(v));
    return make_float2(__uint_as_float(a), __uint_as_float(bb));
}
__device__ __forceinline__ void fma2(u64 &d, u64 a, u64 b){
    asm("fma.rn.f32x2 %0, %1, %2, %0;" : "+l"(d) : "l"(a), "l"(b));
}
__device__ __forceinline__ u64 fma2o(u64 a, u64 b, u64 c){
    u64 d; asm("fma.rn.f32x2 %0, %1, %2, %3;" : "=l"(d) : "l"(a), "l"(b), "l"(c)); return d;
}
__device__ __forceinline__ u64 add2(u64 a, u64 b){
    u64 d; asm("add.rn.f32x2 %0, %1, %2;" : "=l"(d) : "l"(a), "l"(b)); return d;
}

// ---------------- zero accumulators (split so gemm1 is the 4th launch) ------
__global__ void k_zero1(){ int i = blockIdx.x*1024 + threadIdx.x; if (i < B*C) g_Sbo[i]=0.f; }
__global__ void k_zero2(){ int i = blockIdx.x*1024 + threadIdx.x; if (i < B*C) g_SSbo[i]=0.f; }
__global__ void k_zero3(){ int i = threadIdx.x; if (i < D){ g_Sd3[i]=0.f; g_SSd3[i]=0.f; } }

// ================= GEMM1: 128x128 tile, f32x2, gelu + BN1 stats =================
__global__ __launch_bounds__(256) void k_gemm1(const float* __restrict__ x,
                                               const float* __restrict__ w1,
                                               const float* __restrict__ b1){
    const int b = blockIdx.z;
    const int oBase = blockIdx.y<<7, sBase = blockIdx.x<<7;
    const int tx = threadIdx.x, ty = threadIdx.y;   // 16x16
    const int tid = ty*16 + tx;
    __shared__ __align__(16) float Ws[8][132];
    __shared__ __align__(16) float Xs[8][132];

    u64 acc[8][4];
    #pragma unroll
    for (int i=0;i<8;i++){
        #pragma unroll
        for (int j=0;j<4;j++) acc[i][j]=0ull;
    }

    const float* xb = x + (size_t)b*HW*D;
    const int rowL = tid>>1, kpL = (tid&1)*4;
    const float* wp = w1 + (size_t)(oBase+rowL)*D + kpL;
    const float* xp_ = xb + (size_t)(sBase+rowL)*D + kpL;

    float4 wv = *reinterpret_cast<const float4*>(wp);
    float4 xv = *reinterpret_cast<const float4*>(xp_);

    for (int k0=0;k0<D;k0+=8){
        Ws[kpL+0][rowL] = wv.x; Ws[kpL+1][rowL] = wv.y;
        Ws[kpL+2][rowL] = wv.z; Ws[kpL+3][rowL] = wv.w;
        Xs[kpL+0][rowL] = xv.x; Xs[kpL+1][rowL] = xv.y;
        Xs[kpL+2][rowL] = xv.z; Xs[kpL+3][rowL] = xv.w;
        __syncthreads();
        if (k0+8 < D){
            wv = *reinterpret_cast<const float4*>(wp + k0 + 8);
            xv = *reinterpret_cast<const float4*>(xp_ + k0 + 8);
        }
        #pragma unroll
        for (int k=0;k<8;k++){
            float4 wa = *reinterpret_cast<const float4*>(&Ws[k][ty<<2]);
            float4 wb = *reinterpret_cast<const float4*>(&Ws[k][(ty<<2)+64]);
            u64 w2[8];
            w2[0]=splat2(wa.x); w2[1]=splat2(wa.y); w2[2]=splat2(wa.z); w2[3]=splat2(wa.w);
            w2[4]=splat2(wb.x); w2[5]=splat2(wb.y); w2[6]=splat2(wb.z); w2[7]=splat2(wb.w);
            const u64* xpa = reinterpret_cast<const u64*>(&Xs[k][tx<<2]);
            const u64* xpb = reinterpret_cast<const u64*>(&Xs[k][(tx<<2)+64]);
            u64 x2[4];
            x2[0]=xpa[0]; x2[1]=xpa[1]; x2[2]=xpb[0]; x2[3]=xpb[1];
            #pragma unroll
            for (int i=0;i<8;i++){
                #pragma unroll
                for (int j=0;j<4;j++) fma2(acc[i][j], w2[i], x2[j]);
            }
        }
        __syncthreads();
    }
    #pragma unroll
    for (int i=0;i<8;i++){
        int o = oBase + (ty<<2) + (i&3) + ((i>>2)<<6);
        float bias = b1[o];
        float s_=0.f, ss_=0.f;
        float* dst = &g_A[(((size_t)b*C + o)<<10)];
        #pragma unroll
        for (int j=0;j<4;j++){
            int s0 = sBase + (tx<<2) + ((j>>1)<<6) + ((j&1)<<1);
            float2 v = unpack2(acc[i][j]);
            float v0 = gelu_f(v.x + bias), v1 = gelu_f(v.y + bias);
            *reinterpret_cast<float2*>(&dst[s0]) = make_float2(v0, v1);
            s_ += v0 + v1; ss_ += v0*v0 + v1*v1;
        }
        #pragma unroll
        for (int off=8; off; off>>=1){
            s_  += __shfl_down_sync(0xffffffffu, s_,  off, 16);
            ss_ += __shfl_down_sync(0xffffffffu, ss_, off, 16);
        }
        if (tx==0){
            atomicAdd(&g_Sbo [b*C+o], s_);
            atomicAdd(&g_SSbo[b*C+o], ss_);
        }
    }
}

// ---------------- BN1 finalize + GAP ----------------
__global__ void k_bn1fin(const float* __restrict__ g1, const float* __restrict__ be1){
    int o = blockIdx.x*256 + threadIdx.x;
    if (o >= C) return;
    float S=0.f, SS=0.f;
    for (int b=0;b<B;b++){ S += g_Sbo[b*C+o]; SS += g_SSbo[b*C+o]; }
    float m = S*(1.f/8192.f), v = SS*(1.f/8192.f) - m*m;
    float rs = rsqrtf(v + 1e-5f);
    float sc = rs*g1[o], sh = be1[o] - m*sc;
    g_scale1[o]=sc; g_shift1[o]=sh;
    for (int b=0;b<B;b++)
        g_gap[b*C+o] = g_Sbo[b*C+o]*(1.f/1024.f)*sc + sh;
}

// ---------------- dynw FC1: grid 128 (one block per hidden unit) ----------------
__global__ __launch_bounds__(256) void k_dynw1(const float* __restrict__ aw1,
                                               const float* __restrict__ ab1){
    int o = blockIdx.x;
    int b = threadIdx.x>>5, lane = threadIdx.x&31;
    const float4* row = reinterpret_cast<const float4*>(&aw1[(size_t)o*C]);
    const float4* gp  = reinterpret_cast<const float4*>(&g_gap[b*C]);
    float a = 0.f;
    #pragma unroll
    for (int i=0;i<8;i++){
        float4 w = row[lane + 32*i];
        float4 g = gp [lane + 32*i];
        a += w.x*g.x + w.y*g.y + w.z*g.z + w.w*g.w;
    }
    #pragma unroll
    for (int off=16;off;off>>=1) a += __shfl_down_sync(0xffffffffu, a, off);
    if (lane==0) g_h1[b*128+o] = fmaxf(a + ab1[o], 0.f);
}

// ---------------- dynw FC2 + softmax ----------------
__global__ void k_dynw2(const float* __restrict__ aw2, const float* __restrict__ ab2){
    int b = blockIdx.x, tid = threadIdx.x;
    int j = tid>>5, lane = tid&31;
    __shared__ float h1s[128];
    __shared__ float logits[9];
    if (tid < 128) h1s[tid] = g_h1[b*128+tid];
    __syncthreads();
    if (j < 9){
        float4 q = reinterpret_cast<const float4*>(&aw2[j*128])[lane];
        const float* hh = &h1s[lane*4];
        float l = q.x*hh[0] + q.y*hh[1] + q.z*hh[2] + q.w*hh[3];
        #pragma unroll
        for (int off=16;off;off>>=1) l += __shfl_down_sync(0xffffffffu, l, off);
        if (lane==0) logits[j] = l + ab2[j];
    }
    __syncthreads();
    if (tid==0){
        float mx = logits[0];
        for (int jj=1;jj<9;jj++) mx = fmaxf(mx, logits[jj]);
        float e[9], Zs=0.f;
        for (int jj=0;jj<9;jj++){ e[jj]=expf(logits[jj]-mx); Zs+=e[jj]; }
        float inv = 1.f/Zs;
        for (int jj=0;jj<9;jj++) g_kw[b*9+jj] = e[jj]*inv;
    }
}

// ---------------- dynamic depthwise conv + gelu + BN2 stats ----------------
__global__ __launch_bounds__(256) void k_dynconv(){
    const int o = blockIdx.x, b = blockIdx.y;
    const int tid = threadIdx.x;
    const int w = tid>>5, lane = tid&31;
    __shared__ float sm[34][35];
    __shared__ float kwsh[9];
    __shared__ float r4[4][8];
    if (tid < 9) kwsh[tid] = g_kw[b*9 + tid];
    // halo zero
    if (tid < 132){
        if (tid < 34)       sm[0][tid] = 0.f;
        else if (tid < 68)  sm[33][tid-34] = 0.f;
        else if (tid < 100) sm[tid-68+1][0] = 0.f;
        else                sm[tid-100+1][33] = 0.f;
    }
    const float sc = g_scale1[o], sh = g_shift1[o];
    const float* plane = &g_A[((size_t)(b*C + o))<<10];
    {
        int r = tid>>3, c4 = (tid&7)<<2;
        float4 v = *reinterpret_cast<const float4*>(&plane[(r<<5)+c4]);
        sm[r+1][c4+1] = v.x*sc+sh;
        sm[r+1][c4+2] = v.y*sc+sh;
        sm[r+1][c4+3] = v.z*sc+sh;
        sm[r+1][c4+4] = v.w*sc+sh;
    }
    __syncthreads();
    float lsum=0.f, lss=0.f, lmx=-3.4e38f, lmn=3.4e38f;
    #pragma unroll
    for (int q=0;q<4;q++){
        int p = tid + (q<<8);
        int ph = p>>5, pw_ = p&31;
        float a = 0.f;
        #pragma unroll
        for (int i=0;i<3;i++){
            #pragma unroll
            for (int j=0;j<3;j++) a += kwsh[i*3+j]*sm[ph+i][pw_+j];
        }
        float g = gelu_f(a);
        g_B2[(((size_t)(b*C + o))<<10) + p] = g;
        lsum += g; lss += g*g;
        lmx = fmaxf(lmx, g); lmn = fminf(lmn, g);
    }
    #pragma unroll
    for (int off=16;off;off>>=1){
        lsum += __shfl_down_sync(0xffffffffu, lsum, off);
        lss  += __shfl_down_sync(0xffffffffu, lss,  off);
        lmx = fmaxf(lmx, __shfl_down_sync(0xffffffffu, lmx, off));
        lmn = fminf(lmn, __shfl_down_sync(0xffffffffu, lmn, off));
    }
    if (lane==0){ r4[0][w]=lsum; r4[1][w]=lss; r4[2][w]=lmx; r4[3][w]=lmn; }
    __syncthreads();
    if (tid==0){
        float S=0,SS=0,MX=-3.4e38f,MN=3.4e38f;
        for (int i=0;i<8;i++){ S+=r4[0][i]; SS+=r4[1][i]; MX=fmaxf(MX,r4[2][i]); MN=fminf(MN,r4[3][i]); }
        g_S2[b*C+o]=S; g_SS2[b*C+o]=SS; g_Mx2[b*C+o]=MX; g_Mn2[b*C+o]=MN;
    }
}

// ---------------- BN2 finalize ----------------
__global__ void k_bn2fin(const float* __restrict__ g2, const float* __restrict__ be2){
    int o = blockIdx.x*256 + threadIdx.x;
    if (o >= C) return;
    float S=0.f, SS=0.f;
    for (int b=0;b<B;b++){ S += g_S2[b*C+o]; SS += g_SS2[b*C+o]; }
    float m = S*(1.f/8192.f), v = SS*(1.f/8192.f) - m*m;
    float rs = rsqrtf(v + 1e-5f);
    float sc = rs*g2[o], sh = be2[o] - m*sc;
    g_scale2[o]=sc; g_shift2[o]=sh;
    for (int b=0;b<B;b++){
        g_avg2[b*C+o] = g_S2[b*C+o]*(1.f/1024.f)*sc + sh;
        float pre = (sc >= 0.f) ? g_Mx2[b*C+o] : g_Mn2[b*C+o];
        g_max2[b*C+o] = pre*sc + sh;
    }
}

// ---------------- channel attention + Cbd fused ----------------
__global__ __launch_bounds__(512) void k_cattcbd(const float* __restrict__ ca_w1,
                                                 const float* __restrict__ ca_w2,
                                                 const float* __restrict__ pw){
    int b = blockIdx.x, tid = threadIdx.x;
    int w = tid>>5, lane = tid&31;
    __shared__ float sav[C], smv[C], hsum[64], sBc[C];
    for (int i=tid;i<C;i+=512){ sav[i]=g_avg2[b*C+i]; smv[i]=g_max2[b*C+i]; }
    __syncthreads();
    #pragma unroll
    for (int r=0;r<4;r++){
        int o = (w<<2) + r;
        const float* row = &ca_w1[(size_t)o*C];
        float aa=0.f, am=0.f;
        #pragma unroll 8
        for (int c=lane;c<C;c+=32){ float rv=row[c]; aa += rv*sav[c]; am += rv*smv[c]; }
        #pragma unroll
        for (int off=16;off;off>>=1){
            aa += __shfl_down_sync(0xffffffffu, aa, off);
            am += __shfl_down_sync(0xffffffffu, am, off);
        }
        if (lane==0) hsum[o] = fmaxf(aa,0.f) + fmaxf(am,0.f);
    }
    __syncthreads();
    #pragma unroll
    for (int r=0;r<2;r++){
        int c = tid + (r<<9);
        const float4* w2r = reinterpret_cast<const float4*>(&ca_w2[(size_t)c*64]);
        float a = 0.f;
        #pragma unroll
        for (int j=0;j<16;j++){
            float4 q = w2r[j];
            const float* hh = &hsum[j*4];
            a += q.x*hh[0] + q.y*hh[1] + q.z*hh[2] + q.w*hh[3];
        }
        float s = 1.f/(1.f + expf(-a));
        float Av = s*g_scale2[c], Bv = s*g_shift2[c];
        g_Acoef[b*C+c] = Av; g_Bcoef[b*C+c] = Bv; sBc[c] = Bv;
    }
    __syncthreads();
    #pragma unroll
    for (int r=0;r<16;r++){
        int d = w + (r<<4);
        const float* row = &pw[(size_t)d*C];
        float a = 0.f;
        #pragma unroll 8
        for (int c=lane;c<C;c+=32) a += row[c]*sBc[c];
        #pragma unroll
        for (int off=16;off;off>>=1) a += __shfl_down_sync(0xffffffffu, a, off);
        if (lane==0) g_Cbd[b*D+d] = a;
    }
}

// ---------------- spatial mean/max partials (channel-split, float4) ----------------
__global__ __launch_bounds__(1024) void k_spstats(){
    int b = blockIdx.z, csp = blockIdx.y, sblk = blockIdx.x;
    int tid = threadIdx.x;
    int sl = tid & 63, cg = tid >> 6;         // cg 0..15
    int s4 = sblk*64 + sl;                    // float4 index, sblk 0..3
    const float4* base4 = reinterpret_cast<const float4*>(&g_B2[((size_t)b)<<20]);
    const float* Ac = &g_Acoef[b*C];
    const float* Bc = &g_Bcoef[b*C];
    float4 sum = make_float4(0,0,0,0);
    float4 mx  = make_float4(-3.4e38f,-3.4e38f,-3.4e38f,-3.4e38f);
    int c0 = csp*256 + cg*16;
    #pragma unroll 4
    for (int c=c0;c<c0+16;c++){
        float4 v = base4[(c<<8)+s4];
        float a = Ac[c], bb = Bc[c];
        v.x = a*v.x+bb; v.y = a*v.y+bb; v.z = a*v.z+bb; v.w = a*v.w+bb;
        sum.x += v.x; sum.y += v.y; sum.z += v.z; sum.w += v.w;
        mx.x = fmaxf(mx.x,v.x); mx.y = fmaxf(mx.y,v.y);
        mx.z = fmaxf(mx.z,v.z); mx.w = fmaxf(mx.w,v.w);
    }
    __shared__ float4 rs[16][64];
    __shared__ float4 rm[16][64];
    rs[cg][sl] = sum; rm[cg][sl] = mx;
    __syncthreads();
    if (tid < 64){
        float4 S = rs[0][tid], M = rm[0][tid];
        #pragma unroll
        for (int g=1; g<16; g++){
            float4 s2 = rs[g][tid], m2 = rm[g][tid];
            S.x+=s2.x; S.y+=s2.y; S.z+=s2.z; S.w+=s2.w;
            M.x=fmaxf(M.x,m2.x); M.y=fmaxf(M.y,m2.y); M.z=fmaxf(M.z,m2.z); M.w=fmaxf(M.w,m2.w);
        }
        int s4o = sblk*64 + tid;
        reinterpret_cast<float4*>(&g_sppsum[(csp*B + b)*HW])[s4o] = S;
        reinterpret_cast<float4*>(&g_sppmax[(csp*B + b)*HW])[s4o] = M;
    }
}

// ---------------- 7x7 spatial conv + sigmoid (combines partials) ----------------
__global__ void k_spconv(const float* __restrict__ sw, const float* __restrict__ sb){
    int b = blockIdx.x, tid = threadIdx.x;
    __shared__ float sa[1024], sx[1024];
    __shared__ float kw[98];
    for (int i=tid;i<1024;i+=256){
        float s0 = g_sppsum[(0*B+b)*HW+i] + g_sppsum[(1*B+b)*HW+i]
                 + g_sppsum[(2*B+b)*HW+i] + g_sppsum[(3*B+b)*HW+i];
        float m0 = fmaxf(fmaxf(g_sppmax[(0*B+b)*HW+i], g_sppmax[(1*B+b)*HW+i]),
                         fmaxf(g_sppmax[(2*B+b)*HW+i], g_sppmax[(3*B+b)*HW+i]));
        sa[i] = s0*(1.f/1024.f);
        sx[i] = m0;
    }
    if (tid < 98) kw[tid] = sw[tid];
    __syncthreads();
    float bias = sb[0];
    for (int p=tid;p<1024;p+=256){
        int ph = p>>5, pw_ = p&31;
        float acc = bias;
        #pragma unroll
        for (int i=0;i<7;i++){
            int hh = ph + i - 3;
            if ((unsigned)hh >= 32u) continue;
            #pragma unroll
            for (int j=0;j<7;j++){
                int ww = pw_ + j - 3;
                if ((unsigned)ww >= 32u) continue;
                acc += kw[i*7+j]*sa[(hh<<5)+ww] + kw[49+i*7+j]*sx[(hh<<5)+ww];
            }
        }
        g_spatt[b*HW+p] = 1.f/(1.f + expf(-acc));
    }
}

// ================= GEMM2: 128x128 tile, f32x2, folded attention + BN3 stats =================
__global__ __launch_bounds__(256) void k_gemm2(const float* __restrict__ pw,
                                               const float* __restrict__ pb){
    const int b = blockIdx.z;
    const int dBase = blockIdx.y<<7, sBase = blockIdx.x<<7;
    const int tx = threadIdx.x, ty = threadIdx.y;
    const int tid = ty*16 + tx;
    __shared__ __align__(16) float Ws[8][132];
    __shared__ __align__(16) float Xs[8][132];

    u64 acc[8][4];
    #pragma unroll
    for (int i=0;i<8;i++){
        #pragma unroll
        for (int j=0;j<4;j++) acc[i][j]=0ull;
    }

    const float* Ac  = &g_Acoef[b*C];
    const float* src = &g_B2[((size_t)b)<<20];
    const int rowW = tid>>1, kpW = (tid&1)*4;
    const int kX = tid>>5, spX = (tid&31)*4;
    const float* wp = pw + (size_t)(dBase+rowW)*C + kpW;
    const float* xp_ = src + ((size_t)kX<<10) + sBase + spX;

    float4 wv = *reinterpret_cast<const float4*>(wp);
    float4 xv = *reinterpret_cast<const float4*>(xp_);
    float  av = Ac[kX];

    for (int k0=0;k0<C;k0+=8){
        Ws[kpW+0][rowW] = wv.x; Ws[kpW+1][rowW] = wv.y;
        Ws[kpW+2][rowW] = wv.z; Ws[kpW+3][rowW] = wv.w;
        float4 xs = make_float4(xv.x*av, xv.y*av, xv.z*av, xv.w*av);
        *reinterpret_cast<float4*>(&Xs[kX][spX]) = xs;
        __syncthreads();
        if (k0+8 < C){
            wv = *reinterpret_cast<const float4*>(wp + k0 + 8);
            xv = *reinterpret_cast<const float4*>(xp_ + ((size_t)(k0+8)<<10));
            av = Ac[k0+8+kX];
        }
        #pragma unroll
        for (int k=0;k<8;k++){
            float4 wa = *reinterpret_cast<const float4*>(&Ws[k][ty<<2]);
            float4 wb = *reinterpret_cast<const float4*>(&Ws[k][(ty<<2)+64]);
            u64 w2[8];
            w2[0]=splat2(wa.x); w2[1]=splat2(wa.y); w2[2]=splat2(wa.z); w2[3]=splat2(wa.w);
            w2[4]=splat2(wb.x); w2[5]=splat2(wb.y); w2[6]=splat2(wb.z); w2[7]=splat2(wb.w);
            const u64* xpa = reinterpret_cast<const u64*>(&Xs[k][tx<<2]);
            const u64* xpb = reinterpret_cast<const u64*>(&Xs[k][(tx<<2)+64]);
            u64 x2[4];
            x2[0]=xpa[0]; x2[1]=xpa[1]; x2[2]=xpb[0]; x2[3]=xpb[1];
            #pragma unroll
            for (int i=0;i<8;i++){
                #pragma unroll
                for (int j=0;j<4;j++) fma2(acc[i][j], w2[i], x2[j]);
            }
        }
        __syncthreads();
    }
    u64 sp2[4];
    #pragma unroll
    for (int j=0;j<4;j++){
        int s0 = sBase + (tx<<2) + ((j>>1)<<6) + ((j&1)<<1);
        sp2[j] = *reinterpret_cast<const u64*>(&g_spatt[b*HW + s0]);
    }
    #pragma unroll
    for (int i=0;i<8;i++){
        int d = dBase + (ty<<2) + (i&3) + ((i>>2)<<6);
        u64 cb2 = splat2(g_Cbd[b*D + d]);
        u64 pb2 = splat2(pb[d]);
        float s_=0.f, ss_=0.f;
        float* dst = &g_Z[(((size_t)b*D + d)<<10)];
        #pragma unroll
        for (int j=0;j<4;j++){
            int s0 = sBase + (tx<<2) + ((j>>1)<<6) + ((j&1)<<1);
            u64 z2 = fma2o(sp2[j], add2(acc[i][j], cb2), pb2);
            *reinterpret_cast<u64*>(&dst[s0]) = z2;
            float2 z = unpack2(z2);
            s_ += z.x + z.y; ss_ += z.x*z.x + z.y*z.y;
        }
        #pragma unroll
        for (int off=8; off; off>>=1){
            s_  += __shfl_down_sync(0xffffffffu, s_,  off, 16);
            ss_ += __shfl_down_sync(0xffffffffu, ss_, off, 16);
        }
        if (tx==0){
            atomicAdd(&g_Sd3 [d], s_);
            atomicAdd(&g_SSd3[d], ss_);
        }
    }
}

// ---------------- BN3 finalize ----------------
__global__ void k_bn3fin(const float* __restrict__ g3, const float* __restrict__ be3){
    int d = threadIdx.x;
    float m = g_Sd3[d]*(1.f/8192.f);
    float v = g_SSd3[d]*(1.f/8192.f) - m*m;
    float sc = rsqrtf(v + 1e-5f)*g3[d];
    g_scale3[d] = sc;
    g_shift3[d] = be3[d] - m*sc;
}

// ---------------- transpose + BN3 + residual ----------------
__global__ void k_out(const float* __restrict__ x, float* __restrict__ out){
    const int b = blockIdx.z;
    const int dB = blockIdx.y<<5, sB = blockIdx.x<<5;
    const int tx = threadIdx.x, ty = threadIdx.y;
    __shared__ float sm[32][33];
    #pragma unroll
    for (int r=0;r<4;r++){
        int dd = ty + (r<<3);
        sm[dd][tx] = g_Z[(((size_t)b*D + dB + dd)<<10) + sB + tx];
    }
    __syncthreads();
    int d = dB + tx;
    float sc = g_scale3[d], sh = g_shift3[d];
    #pragma unroll
    for (int r=0;r<4;r++){
        int ss = ty + (r<<3);
        size_t oi = ((size_t)(b*HW) + sB + ss)*D + d;
        out[oi] = x[oi] + sm[tx][ss]*sc + sh;
    }
}

extern "C" void kernel_launch(void* const* d_in, const int* in_sizes, int n_in,
                              void* d_out, int out_size){
    const float* x     = (const float*)d_in[0];
    const float* w1    = (const float*)d_in[1];
    const float* b1    = (const float*)d_in[2];
    const float* g1    = (const float*)d_in[3];
    const float* be1   = (const float*)d_in[4];
    const float* aw1   = (const float*)d_in[5];
    const float* ab1   = (const float*)d_in[6];
    const float* aw2   = (const float*)d_in[7];
    const float* ab2   = (const float*)d_in[8];
    const float* g2    = (const float*)d_in[9];
    const float* be2   = (const float*)d_in[10];
    const float* ca_w1 = (const float*)d_in[11];
    const float* ca_w2 = (const float*)d_in[12];
    const float* pw    = (const float*)d_in[13];
    const float* pb    = (const float*)d_in[14];
    const float* g3    = (const float*)d_in[15];
    const float* be3   = (const float*)d_in[16];
    const float* sw    = (const float*)d_in[17];
    const float* sb    = (const float*)d_in[18];
    float* out = (float*)d_out;

    k_zero1   <<<8, 1024>>>();
    k_zero2   <<<8, 1024>>>();
    k_zero3   <<<1, 512>>>();
    k_gemm1   <<<dim3(8,8,B), dim3(16,16)>>>(x, w1, b1);
    k_bn1fin  <<<4, 256>>>(g1, be1);
    k_dynw1   <<<128, 256>>>(aw1, ab1);
    k_dynw2   <<<B, 288>>>(aw2, ab2);
    k_dynconv <<<dim3(C,B), 256>>>();
    k_bn2fin  <<<4, 256>>>(g2, be2);
    k_cattcbd <<<B, 512>>>(ca_w1, ca_w2, pw);
    k_spstats <<<dim3(4,4,B), 1024>>>();
    k_spconv  <<<B, 256>>>(sw, sb);
    k_gemm2   <<<dim3(8,2,B), dim3(16,16)>>>(pw, pb);
    k_bn3fin  <<<1, 256>>>(g3, be3);
    k_out     <<<dim3(32,8,B), dim3(32,8)>>>(x, out);
}